// round 3
// baseline (speedup 1.0000x reference)
#include <cuda_runtime.h>

#define N_NODES 100000
#define N_EDGES 1600000
#define HMW 32            // concatenated mu(16) | logstd(16)
#define OUTC 16

// ---------------- scratch (device globals; no allocations allowed) -------------
__device__ float g_deg [N_NODES];          // in-degree count (dst)
__device__ float g_acc0[N_NODES * 2];      // layer-1 aggregation of dis*x
__device__ float g_gvec[N_NODES * HMW];    // g = dis * (h @ [Wmu|Wls])
__device__ float g_acc1[N_NODES * HMW];    // layer-2 aggregation of g[src]
__device__ int   g_is64;                   // edge_index dtype flag

// ---------------- vectorized L2 reductions (sm_90+) -----------------------------
__device__ __forceinline__ void red_add_v4(float* addr, float4 v) {
    asm volatile("red.global.add.v4.f32 [%0], {%1, %2, %3, %4};"
                 :: "l"(addr), "f"(v.x), "f"(v.y), "f"(v.z), "f"(v.w) : "memory");
}
__device__ __forceinline__ void red_add_v2(float* addr, float a, float b) {
    asm volatile("red.global.add.v2.f32 [%0], {%1, %2};"
                 :: "l"(addr), "f"(a), "f"(b) : "memory");
}

__device__ __forceinline__ void load_edge(const void* ei, int e, int& src, int& dst) {
    if (g_is64) {
        const long long* p = (const long long*)ei;
        src = (int)p[e];
        dst = (int)p[N_EDGES + e];
    } else {
        const int* p = (const int*)ei;
        src = p[e];
        dst = p[N_EDGES + e];
    }
}

// ---------------- init: block 0 detects dtype; all blocks zero deg + acc0 -------
// int64 indices < 100000 have all-zero high words; int32 data makes them edge
// values (zero with prob ~1e-5 each) -> OR over 4096 words is a safe detector.
__global__ void k_init(const unsigned* ei_words) {
    if (blockIdx.x == 0) {
        __shared__ unsigned s_or[256];
        unsigned v = 0;
        for (int i = threadIdx.x; i < 4096; i += 256)
            v |= ei_words[2 * i + 1];
        s_or[threadIdx.x] = v;
        __syncthreads();
        for (int s = 128; s > 0; s >>= 1) {
            if (threadIdx.x < s) s_or[threadIdx.x] |= s_or[threadIdx.x + s];
            __syncthreads();
        }
        if (threadIdx.x == 0) g_is64 = (s_or[0] == 0u) ? 1 : 0;
    }
    const float4 z = make_float4(0.f, 0.f, 0.f, 0.f);
    int i = blockIdx.x * 256 + threadIdx.x;
    if (i < N_NODES * 2 / 4) ((float4*)g_acc0)[i] = z;           // 50000 float4
    if (i < N_NODES / 4)     ((float4*)g_deg )[i] = z;           // 25000 float4
}

// ---------------- degree (count of dst occurrences) -----------------------------
__global__ void k_deg(const void* ei) {
    int e = blockIdx.x * 256 + threadIdx.x;
    if (e >= N_EDGES) return;
    int dst;
    if (g_is64) dst = (int)((const long long*)ei)[N_EDGES + e];
    else        dst = ((const int*)ei)[N_EDGES + e];
    atomicAdd(&g_deg[dst], 1.0f);
}

// ---------------- layer-1 scatter: acc0[dst] += dis[src] * x[src]  (2 feats) ----
// dis computed on the fly from deg (MUFU.RSQ is cheaper than a launch)
__global__ void k_scatter0(const void* ei, const float* __restrict__ x) {
    int e = blockIdx.x * 256 + threadIdx.x;
    if (e >= N_EDGES) return;
    int src, dst;
    load_edge(ei, e, src, dst);
    float ds = rsqrtf(1.0f + g_deg[src]);
    float2 xv = ((const float2*)x)[src];
    red_add_v2(&g_acc0[2 * dst], ds * xv.x, ds * xv.y);
}

// ---------------- dense: h = relu(aggX @ W1 + b1); g = dis * (h @ [Wmu|Wls]) ----
// one warp per node; 8 nodes per 256-thread block; also zeroes acc1 rows
__global__ void k_hidden(const float* __restrict__ x, const float* __restrict__ W1,
                         const float* __restrict__ b1,
                         const float* __restrict__ Wmu, const float* __restrict__ Wls) {
    __shared__ float sW[64][HMW];   // concatenated projection, 8KB
    __shared__ float sW1[2][64];
    __shared__ float sb1[64];
    __shared__ float sh[8][64];

    int t = threadIdx.x;
    // zero this block's acc1 slice (runs before scatter1 by kernel ordering)
    g_acc1[blockIdx.x * 256 + t] = 0.0f;

    for (int i = t; i < 64 * HMW; i += 256) {
        int k = i >> 5, j = i & 31;
        sW[k][j] = (j < OUTC) ? Wmu[k * OUTC + j] : Wls[k * OUTC + (j - OUTC)];
    }
    if (t < 128) sW1[t >> 6][t & 63] = W1[t];
    if (t < 64)  sb1[t] = b1[t];
    __syncthreads();

    int w = t >> 5, lane = t & 31;
    int n = blockIdx.x * 8 + w;
    if (n < N_NODES) {
        float d  = rsqrtf(1.0f + g_deg[n]);
        float d2 = d * d;
        float a0 = d * g_acc0[2 * n + 0] + d2 * x[2 * n + 0];
        float a1 = d * g_acc0[2 * n + 1] + d2 * x[2 * n + 1];
        float h0 = fmaxf(0.0f, a0 * sW1[0][lane]      + a1 * sW1[1][lane]      + sb1[lane]);
        float h1 = fmaxf(0.0f, a0 * sW1[0][lane + 32] + a1 * sW1[1][lane + 32] + sb1[lane + 32]);
        sh[w][lane]      = h0;
        sh[w][lane + 32] = h1;
        __syncwarp();
        float s = 0.0f;
        #pragma unroll
        for (int k = 0; k < 64; k++)
            s += sh[w][k] * sW[k][lane];   // sh broadcast, sW conflict-free
        g_gvec[n * HMW + lane] = d * s;
    }
}

// ---------------- layer-2 scatter: acc1[dst][:] += g[src][:]  (32 feats) --------
// 4 threads per edge; each does 2x (float4 gather + red.v4). Same REDG count as
// before, half the index loads and thread count.
__global__ void k_scatter1(const void* ei) {
    long long tid = (long long)blockIdx.x * 256 + threadIdx.x;
    if (tid >= (long long)N_EDGES * 4) return;
    int e = (int)(tid >> 2), q = (int)(tid & 3);
    int src, dst;
    load_edge(ei, e, src, dst);
    const float4* gs = (const float4*)g_gvec + src * 8;
    float4 v0 = gs[q];
    float4 v1 = gs[q + 4];
    red_add_v4(&g_acc1[dst * HMW + q * 4], v0);
    red_add_v4(&g_acc1[dst * HMW + 16 + q * 4], v1);
}

// ---------------- epilogue: out = dis*(acc1 + g) + bias; split mu / logstd ------
__global__ void k_out(const float* __restrict__ bmu, const float* __restrict__ bls,
                      float* __restrict__ out) {
    int tid = blockIdx.x * 256 + threadIdx.x;
    if (tid >= N_NODES * HMW) return;
    int n = tid >> 5, j = tid & 31;
    float v = rsqrtf(1.0f + g_deg[n]) * (g_acc1[tid] + g_gvec[tid]);
    if (j < OUTC) out[n * OUTC + j] = v + bmu[j];
    else          out[N_NODES * OUTC + n * OUTC + (j - OUTC)] = v + bls[j - OUTC];
}

extern "C" void kernel_launch(void* const* d_in, const int* in_sizes, int n_in,
                              void* d_out, int out_size) {
    const float* x    = (const float*)d_in[0];
    const void*  ei   = d_in[1];                 // int32 or int64, detected on device
    const float* W1   = (const float*)d_in[2];
    const float* b1   = (const float*)d_in[3];
    const float* Wmu  = (const float*)d_in[4];
    const float* bmu  = (const float*)d_in[5];
    const float* Wls  = (const float*)d_in[6];
    const float* bls  = (const float*)d_in[7];
    float* out = (float*)d_out;

    const int IB  = (N_NODES * 2 / 4 + 255) / 256;        // 196 (covers deg too)
    const int EB  = (N_EDGES + 255) / 256;                // 6250
    const int HB  = (N_NODES + 7) / 8;                    // 12500
    const int OB  = (N_NODES * HMW + 255) / 256;          // 12500
    const int S1B = (int)(((long long)N_EDGES * 4 + 255) / 256);  // 25000

    k_init<<<IB, 256>>>((const unsigned*)ei);
    k_deg<<<EB, 256>>>(ei);
    k_scatter0<<<EB, 256>>>(ei, x);
    k_hidden<<<HB, 256>>>(x, W1, b1, Wmu, Wls);
    k_scatter1<<<S1B, 256>>>(ei);
    k_out<<<OB, 256>>>(bmu, bls, out);
}

// round 4
// speedup vs baseline: 1.3255x; 1.3255x over previous
#include <cuda_runtime.h>

#define N_NODES 100000
#define N_EDGES 1600000
#define HMW 32            // concatenated mu(16) | logstd(16)
#define OUTC 16

// ---------------- scratch (device globals; no allocations allowed) -------------
__device__ float g_deg [N_NODES];          // in-degree count (dst)
__device__ float g_acc0[N_NODES * 2];      // layer-1 aggregation of dis*x
__device__ float g_gvec[N_NODES * HMW];    // g = dis * (h @ [Wmu|Wls])
__device__ float g_acc1[N_NODES * HMW];    // layer-2 aggregation of g[src]
__device__ int   g_is64;                   // edge_index dtype flag

// ---------------- vectorized L2 reductions (sm_90+) -----------------------------
__device__ __forceinline__ void red_add_v4(float* addr, float4 v) {
    asm volatile("red.global.add.v4.f32 [%0], {%1, %2, %3, %4};"
                 :: "l"(addr), "f"(v.x), "f"(v.y), "f"(v.z), "f"(v.w) : "memory");
}
__device__ __forceinline__ void red_add_v2(float* addr, float a, float b) {
    asm volatile("red.global.add.v2.f32 [%0], {%1, %2};"
                 :: "l"(addr), "f"(a), "f"(b) : "memory");
}

__device__ __forceinline__ void load_edge(const void* ei, int e, int& src, int& dst) {
    if (g_is64) {
        const long long* p = (const long long*)ei;
        src = (int)p[e];
        dst = (int)p[N_EDGES + e];
    } else {
        const int* p = (const int*)ei;
        src = p[e];
        dst = p[N_EDGES + e];
    }
}

// ---------------- init: block 0 detects dtype; all blocks zero scratch ----------
// int64 indices < 100000 have all-zero high words -> OR over 4096 words detects.
__global__ void k_init(const unsigned* ei_words) {
    if (blockIdx.x == 0) {
        __shared__ unsigned s_or[256];
        unsigned v = 0;
        for (int i = threadIdx.x; i < 4096; i += 256)
            v |= ei_words[2 * i + 1];
        s_or[threadIdx.x] = v;
        __syncthreads();
        for (int s = 128; s > 0; s >>= 1) {
            if (threadIdx.x < s) s_or[threadIdx.x] |= s_or[threadIdx.x + s];
            __syncthreads();
        }
        if (threadIdx.x == 0) g_is64 = (s_or[0] == 0u) ? 1 : 0;
    }
    const float4 z = make_float4(0.f, 0.f, 0.f, 0.f);
    int i = blockIdx.x * 256 + threadIdx.x;
    if (i < N_NODES * HMW / 4) ((float4*)g_acc1)[i] = z;   // 800000 float4
    if (i < N_NODES * 2 / 4)   ((float4*)g_acc0)[i] = z;   // 50000 float4
    if (i < N_NODES / 4)       ((float4*)g_deg )[i] = z;   // 25000 float4
}

// ---------------- degree (count of dst occurrences) -----------------------------
__global__ void k_deg(const void* ei) {
    int e = blockIdx.x * 256 + threadIdx.x;
    if (e >= N_EDGES) return;
    int dst;
    if (g_is64) dst = (int)((const long long*)ei)[N_EDGES + e];
    else        dst = ((const int*)ei)[N_EDGES + e];
    atomicAdd(&g_deg[dst], 1.0f);
}

// ---------------- layer-1 scatter: acc0[dst] += dis[src] * x[src]  (2 feats) ----
__global__ void k_scatter0(const void* ei, const float* __restrict__ x) {
    int e = blockIdx.x * 256 + threadIdx.x;
    if (e >= N_EDGES) return;
    int src, dst;
    load_edge(ei, e, src, dst);
    float ds = rsqrtf(1.0f + g_deg[src]);
    float2 xv = ((const float2*)x)[src];
    red_add_v2(&g_acc0[2 * dst], ds * xv.x, ds * xv.y);
}

// ---------------- dense: h = relu(aggX @ W1 + b1); g = dis * (h @ [Wmu|Wls]) ----
// ONE THREAD PER NODE, acc[32] in registers, weights read as BROADCAST float4
// LDS (one crossbar phase serves the whole warp). Smem traffic ~25MB total
// vs 800MB for the warp-per-node version.
__global__ void __launch_bounds__(256) k_hidden(
        const float* __restrict__ x, const float* __restrict__ W1,
        const float* __restrict__ b1,
        const float* __restrict__ Wmu, const float* __restrict__ Wls) {
    __shared__ float4 sW4[64][8];   // [k][j/4] of concatenated [Wmu|Wls], 8KB
    __shared__ float4 sWb[64];      // (W1[0][k], W1[1][k], b1[k], 0)

    int t = threadIdx.x;
    for (int i = t; i < 64 * 8; i += 256) {
        int k = i >> 3, q = i & 7, j = q * 4;
        float4 v;
        v.x = (j + 0 < OUTC) ? Wmu[k * OUTC + j + 0] : Wls[k * OUTC + j + 0 - OUTC];
        v.y = (j + 1 < OUTC) ? Wmu[k * OUTC + j + 1] : Wls[k * OUTC + j + 1 - OUTC];
        v.z = (j + 2 < OUTC) ? Wmu[k * OUTC + j + 2] : Wls[k * OUTC + j + 2 - OUTC];
        v.w = (j + 3 < OUTC) ? Wmu[k * OUTC + j + 3] : Wls[k * OUTC + j + 3 - OUTC];
        sW4[k][q] = v;
    }
    if (t < 64) sWb[t] = make_float4(W1[t], W1[64 + t], b1[t], 0.0f);
    __syncthreads();

    int n = blockIdx.x * 256 + t;
    if (n >= N_NODES) return;

    float d  = rsqrtf(1.0f + g_deg[n]);
    float d2 = d * d;
    float2 xv = ((const float2*)x)[n];
    float2 av = ((const float2*)g_acc0)[n];
    float a0 = d * av.x + d2 * xv.x;
    float a1 = d * av.y + d2 * xv.y;

    float acc[HMW];
    #pragma unroll
    for (int j = 0; j < HMW; j++) acc[j] = 0.0f;

    #pragma unroll 8
    for (int k = 0; k < 64; k++) {
        float4 wb = sWb[k];
        float hk = fmaxf(0.0f, fmaf(a0, wb.x, fmaf(a1, wb.y, wb.z)));
        #pragma unroll
        for (int q = 0; q < 8; q++) {
            float4 w = sW4[k][q];
            acc[q * 4 + 0] = fmaf(hk, w.x, acc[q * 4 + 0]);
            acc[q * 4 + 1] = fmaf(hk, w.y, acc[q * 4 + 1]);
            acc[q * 4 + 2] = fmaf(hk, w.z, acc[q * 4 + 2]);
            acc[q * 4 + 3] = fmaf(hk, w.w, acc[q * 4 + 3]);
        }
    }

    float4* gout = (float4*)(g_gvec + n * HMW);
    #pragma unroll
    for (int q = 0; q < 8; q++)
        gout[q] = make_float4(d * acc[q * 4 + 0], d * acc[q * 4 + 1],
                              d * acc[q * 4 + 2], d * acc[q * 4 + 3]);
}

// ---------------- layer-2 scatter: acc1[dst][:] += g[src][:]  (32 feats) --------
// 8 threads per edge; each does one float4 gather + one independent red.v4
__global__ void k_scatter1(const void* ei) {
    long long tid = (long long)blockIdx.x * 256 + threadIdx.x;
    if (tid >= (long long)N_EDGES * 8) return;
    int e = (int)(tid >> 3), q = (int)(tid & 7);
    int src, dst;
    load_edge(ei, e, src, dst);
    float4 v = ((const float4*)g_gvec)[src * 8 + q];
    red_add_v4(&g_acc1[dst * HMW + q * 4], v);
}

// ---------------- epilogue: out = dis*(acc1 + g) + bias; split mu / logstd ------
__global__ void k_out(const float* __restrict__ bmu, const float* __restrict__ bls,
                      float* __restrict__ out) {
    int tid = blockIdx.x * 256 + threadIdx.x;
    if (tid >= N_NODES * HMW) return;
    int n = tid >> 5, j = tid & 31;
    float v = rsqrtf(1.0f + g_deg[n]) * (g_acc1[tid] + g_gvec[tid]);
    if (j < OUTC) out[n * OUTC + j] = v + bmu[j];
    else          out[N_NODES * OUTC + n * OUTC + (j - OUTC)] = v + bls[j - OUTC];
}

extern "C" void kernel_launch(void* const* d_in, const int* in_sizes, int n_in,
                              void* d_out, int out_size) {
    const float* x    = (const float*)d_in[0];
    const void*  ei   = d_in[1];                 // int32 or int64, detected on device
    const float* W1   = (const float*)d_in[2];
    const float* b1   = (const float*)d_in[3];
    const float* Wmu  = (const float*)d_in[4];
    const float* bmu  = (const float*)d_in[5];
    const float* Wls  = (const float*)d_in[6];
    const float* bls  = (const float*)d_in[7];
    float* out = (float*)d_out;

    const int IB  = (N_NODES * HMW / 4 + 255) / 256;      // 3125 (covers all zeroed ranges)
    const int EB  = (N_EDGES + 255) / 256;                // 6250
    const int HB  = (N_NODES + 255) / 256;                // 391
    const int OB  = (N_NODES * HMW + 255) / 256;          // 12500
    const int S1B = (int)(((long long)N_EDGES * 8 + 255) / 256);  // 50000

    k_init<<<IB, 256>>>((const unsigned*)ei);
    k_deg<<<EB, 256>>>(ei);
    k_scatter0<<<EB, 256>>>(ei, x);
    k_hidden<<<HB, 256>>>(x, W1, b1, Wmu, Wls);
    k_scatter1<<<S1B, 256>>>(ei);
    k_out<<<OB, 256>>>(bmu, bls, out);
}